// round 8
// baseline (speedup 1.0000x reference)
#include <cuda_runtime.h>
#include <math.h>

#define Bb   2
#define Tt   2048
#define ROWS (Bb*Tt)     // 4096
#define PW   1536        // packed width: q|k0|k1|v0|v1|gate
#define CL   32          // real steps per chunk
#define NV   64          // virtual steps per chunk (2*CL)
#define NCH  64          // chunks per batch
#define CHT  (Bb*NCH)    // 128 total chunks

// ---------------- scratch (static device globals; no runtime alloc) ----------------
__device__ float g_Wpack[256 * PW];
__device__ float g_pack[(size_t)ROWS * PW];
__device__ float g_qn [ROWS * 256];
__device__ float g_k0n[ROWS * 256];
__device__ float g_k1n[ROWS * 256];
__device__ float g_v  [ROWS * 2 * 256];          // beta-scaled silu'd v
__device__ float g_sc [ROWS * 4];                // 0: g(log decay), 1: b0, 2: b1
__device__ float g_o  [ROWS * 256];
// chunk workspaces
__device__ float g_gram[(size_t)CHT * 96 * 64];  // rows 0..63: k_i.k_j ; 64..95: q_t.k_j
__device__ float g_T   [(size_t)CHT * NV * NV];  // (I+M)^-1, unit lower triangular
__device__ float g_AT  [(size_t)CHT * CL * NV];  // Attn * T
__device__ float g_aux [(size_t)CHT * 192];      // 0..63 bA, 64..127 rhoe, 128..159 A_t, 160 aend
__device__ float g_BK  [(size_t)CHT * NV * 256]; // bA_i * k_i
__device__ float g_AQ  [(size_t)CHT * CL * 256]; // A_t * q_t
__device__ float g_CKT [(size_t)CHT * NV * 256]; // (T^T diag(rhoe) K)[j][d]

__device__ __forceinline__ float warp_sum(float v) {
    #pragma unroll
    for (int off = 16; off; off >>= 1)
        v += __shfl_xor_sync(0xffffffffu, v, off);
    return v;
}

// ---------------- weight packing ----------------
__global__ void pack_weights(const float* __restrict__ Wq, const float* __restrict__ Wk,
                             const float* __restrict__ Wv, const float* __restrict__ Wg)
{
    int d = blockIdx.x, c = threadIdx.x;
    g_Wpack[d*PW + c]        = Wq[d*256 + c];
    g_Wpack[d*PW + 256 + c]  = Wk[d*256 + c];
    g_Wpack[d*PW + 512 + c]  = Wk[65536 + d*256 + c];
    g_Wpack[d*PW + 768 + c]  = Wv[d*256 + c];
    g_Wpack[d*PW + 1024 + c] = Wv[65536 + d*256 + c];
    g_Wpack[d*PW + 1280 + c] = Wg[d*256 + c];
}

// ---------------- fp32 tiled GEMM: C[M,N] = A[M,256] * B[256,N] ----------------
__global__ __launch_bounds__(256)
void gemm_kernel(const float* __restrict__ A, const float* __restrict__ B,
                 float* __restrict__ C, int lda, int ldb, int ldc)
{
    __shared__ float As[32][68];
    __shared__ float Bs[32][64];
    int bm = blockIdx.x * 64, bn = blockIdx.y * 64;
    int tid = threadIdx.x;
    int tx = tid & 15, ty = tid >> 4;
    float acc[4][4] = {};
    for (int k0 = 0; k0 < 256; k0 += 32) {
        #pragma unroll
        for (int i = 0; i < 2; i++) {
            int idx = tid + i*256;
            int ar = idx >> 3, ac = (idx & 7) << 2;
            float4 av = *(const float4*)(A + (size_t)(bm+ar)*lda + k0 + ac);
            As[ac+0][ar] = av.x; As[ac+1][ar] = av.y;
            As[ac+2][ar] = av.z; As[ac+3][ar] = av.w;
            int br = idx >> 4, bc = (idx & 15) << 2;
            *(float4*)(&Bs[br][bc]) = *(const float4*)(B + (size_t)(k0+br)*ldb + bn + bc);
        }
        __syncthreads();
        #pragma unroll
        for (int k = 0; k < 32; k++) {
            float a[4], b[4];
            *(float4*)a = *(const float4*)(&As[k][ty<<2]);
            *(float4*)b = *(const float4*)(&Bs[k][tx<<2]);
            #pragma unroll
            for (int i = 0; i < 4; i++)
                #pragma unroll
                for (int j = 0; j < 4; j++)
                    acc[i][j] = fmaf(a[i], b[j], acc[i][j]);
        }
        __syncthreads();
    }
    #pragma unroll
    for (int i = 0; i < 4; i++)
        *(float4*)(C + (size_t)(bm + (ty<<2) + i)*ldc + bn + (tx<<2)) = *(float4*)acc[i];
}

// ---------------- beta / g projections ----------------
__global__ void proj_small(const float* __restrict__ x, const float* __restrict__ Wb,
                           const float* __restrict__ Wa, const float* __restrict__ A_log,
                           const float* __restrict__ dt_bias)
{
    int row  = blockIdx.x * 4 + (threadIdx.x >> 5);
    int lane = threadIdx.x & 31;
    const float* xr = x + (size_t)row * 256;
    float a0 = 0.f, a1 = 0.f, a2 = 0.f;
    #pragma unroll
    for (int r = 0; r < 8; r++) {
        int d = lane + 32*r;
        float xv = xr[d];
        a0 = fmaf(xv, Wb[d],       a0);
        a1 = fmaf(xv, Wb[256 + d], a1);
        a2 = fmaf(xv, Wa[d],       a2);
    }
    a0 = warp_sum(a0); a1 = warp_sum(a1); a2 = warp_sum(a2);
    if (lane == 0) {
        float z  = a2 + dt_bias[0];
        float sp = (z > 20.f) ? z : log1pf(expf(z));
        g_sc[row*4 + 0] = -expf(A_log[0]) * sp;     // g (log decay)
        g_sc[row*4 + 1] = 1.f / (1.f + expf(-a0));  // b0
        g_sc[row*4 + 2] = 1.f / (1.f + expf(-a1));  // b1
    }
}

// ---------------- causal conv4 + silu + l2norm; v scaled by beta ----------------
__global__ __launch_bounds__(256)
void conv_norm_kernel(const float* __restrict__ qw, const float* __restrict__ kw,
                      const float* __restrict__ vw)
{
    int row = blockIdx.x;
    int t   = row & (Tt - 1);
    int c   = threadIdx.x;
    int lane = c & 31, w = c >> 5;
    float acc[5] = {0.f, 0.f, 0.f, 0.f, 0.f};
    #pragma unroll
    for (int i = 0; i < 4; i++) {
        if (t - 3 + i < 0) continue;
        const float* Pr = g_pack + (size_t)(row - 3 + i) * PW;
        acc[0] = fmaf(Pr[c],        qw[c*4 + i],          acc[0]);
        acc[1] = fmaf(Pr[256 + c],  kw[c*4 + i],          acc[1]);
        acc[2] = fmaf(Pr[512 + c],  kw[(256 + c)*4 + i],  acc[2]);
        acc[3] = fmaf(Pr[768 + c],  vw[c*4 + i],          acc[3]);
        acc[4] = fmaf(Pr[1024 + c], vw[(256 + c)*4 + i],  acc[4]);
    }
    #pragma unroll
    for (int m = 0; m < 5; m++) acc[m] = acc[m] / (1.f + expf(-acc[m]));  // silu

    __shared__ float red[3][8];
    float r0 = warp_sum(acc[0]*acc[0]);
    float r1 = warp_sum(acc[1]*acc[1]);
    float r2 = warp_sum(acc[2]*acc[2]);
    if (lane == 0) { red[0][w] = r0; red[1][w] = r1; red[2][w] = r2; }
    __syncthreads();
    float s0 = 0.f, s1 = 0.f, s2 = 0.f;
    #pragma unroll
    for (int i = 0; i < 8; i++) { s0 += red[0][i]; s1 += red[1][i]; s2 += red[2][i]; }

    g_qn [row*256 + c] = acc[0] * rsqrtf(s0 + 1e-6f);
    g_k0n[row*256 + c] = acc[1] * rsqrtf(s1 + 1e-6f);
    g_k1n[row*256 + c] = acc[2] * rsqrtf(s2 + 1e-6f);
    float b0 = g_sc[row*4 + 1], b1 = g_sc[row*4 + 2];
    g_v[(size_t)(row*2 + 0)*256 + c] = acc[3] * b0;
    g_v[(size_t)(row*2 + 1)*256 + c] = acc[4] * b1;
}

// ---------------- per-chunk Gram: C[96][64] = [Kv; Q] * Kv^T ----------------
__global__ __launch_bounds__(256)
void gram_chunk()
{
    int cg = blockIdx.x;
    int b = cg >> 6, cl = cg & 63;
    int base = b*Tt + cl*CL;
    int tid = threadIdx.x;
    int tx = tid & 15, ty = tid >> 4;
    __shared__ float As[96][68];
    __shared__ float Bt[64][68];   // transposed: Bt[k][j] = Kv[j][k]
    float acc[6][4] = {};
    for (int kk = 0; kk < 256; kk += 64) {
        for (int idx = tid; idx < 96*64; idx += 256) {
            int row = idx >> 6, c = idx & 63;
            float val;
            if (row < 64) {
                int t = row >> 1;
                const float* src = (row & 1) ? g_k1n : g_k0n;
                val = src[(size_t)(base+t)*256 + kk + c];
            } else {
                val = g_qn[(size_t)(base + row - 64)*256 + kk + c];
            }
            As[row][c] = val;
        }
        for (int idx = tid; idx < 64*64; idx += 256) {
            int j = idx >> 6, c = idx & 63;
            int t = j >> 1;
            const float* src = (j & 1) ? g_k1n : g_k0n;
            Bt[c][j] = src[(size_t)(base+t)*256 + kk + c];
        }
        __syncthreads();
        #pragma unroll 8
        for (int k = 0; k < 64; k++) {
            float4 bv = *(const float4*)&Bt[k][tx*4];
            #pragma unroll
            for (int m = 0; m < 6; m++) {
                float a = As[ty*6 + m][k];
                acc[m][0] = fmaf(a, bv.x, acc[m][0]);
                acc[m][1] = fmaf(a, bv.y, acc[m][1]);
                acc[m][2] = fmaf(a, bv.z, acc[m][2]);
                acc[m][3] = fmaf(a, bv.w, acc[m][3]);
            }
        }
        __syncthreads();
    }
    #pragma unroll
    for (int m = 0; m < 6; m++)
        *(float4*)(g_gram + (size_t)cg*6144 + (ty*6+m)*64 + tx*4) = *(float4*)acc[m];
}

// ---------------- per-chunk: M build, T=(I+M)^-1, AT=Attn*T, aux scalars ----------
__global__ __launch_bounds__(64)
void solve_chunk()
{
    int cg = blockIdx.x;
    int b = cg >> 6, cl = cg & 63;
    int base = b*Tt + cl*CL;
    int tid = threadIdx.x;
    __shared__ float Lg[CL];
    __shared__ float M[NV][65];
    __shared__ float X[NV][65];
    __shared__ float At[CL][65];
    if (tid == 0) {
        float a = 0.f;
        for (int t = 0; t < CL; t++) { a += g_sc[(base+t)*4]; Lg[t] = a; }
    }
    __syncthreads();
    {
        int i = tid, ti = i >> 1;
        float bi = g_sc[(base+ti)*4 + 1 + (i & 1)];
        const float* G = g_gram + (size_t)cg*6144 + i*64;
        for (int j = 0; j < i; j++) {
            int tj = j >> 1;
            M[i][j] = bi * expf(Lg[ti] - Lg[tj]) * G[j];
        }
    }
    __syncthreads();
    {
        int j = tid;
        for (int i = 0; i < NV; i++) {
            float acc;
            if (i < j)       acc = 0.f;
            else if (i == j) acc = 1.f;
            else {
                acc = 0.f;
                for (int jp = j; jp < i; jp++) acc -= M[i][jp] * X[jp][j];
            }
            X[i][j] = acc;
        }
    }
    __syncthreads();
    for (int i = 0; i < NV; i++)
        g_T[(size_t)cg*4096 + i*64 + tid] = X[i][tid];
    {
        int j = tid, tj = j >> 1;
        for (int t = 0; t < CL; t++) {
            float v = 0.f;
            if (j <= 2*t + 1)
                v = expf(Lg[t] - Lg[tj]) * g_gram[(size_t)cg*6144 + (64+t)*64 + j];
            At[t][j] = v;
        }
    }
    __syncthreads();
    {
        int j = tid;
        for (int t = 0; t < CL; t++) {
            float acc = 0.f;
            for (int i = j; i < NV; i++) acc += At[t][i] * X[i][j];
            g_AT[(size_t)cg*2048 + t*64 + j] = acc;
        }
    }
    {
        int i = tid, ti = i >> 1;
        float bi = g_sc[(base+ti)*4 + 1 + (i & 1)];
        g_aux[(size_t)cg*192 + i]      = bi * expf(Lg[ti]);          // bA
        g_aux[(size_t)cg*192 + 64 + i] = expf(Lg[CL-1] - Lg[ti]);    // rhoe
        if (i < CL) g_aux[(size_t)cg*192 + 128 + i] = expf(Lg[i]);   // A_t
        if (i == 0) g_aux[(size_t)cg*192 + 160]     = expf(Lg[CL-1]);// aend
    }
}

// ---------------- per-chunk: BK, AQ, CKT ----------------
__global__ __launch_bounds__(256)
void build_chunk()
{
    int cg = blockIdx.x;
    int b = cg >> 6, cl = cg & 63;
    int base = b*Tt + cl*CL;
    int d = threadIdx.x;
    __shared__ float Tsc[NV][68];  // T[i][j] * rhoe[i]
    for (int idx = d; idx < 4096; idx += 256) {
        int i = idx >> 6, j = idx & 63;
        Tsc[i][j] = g_T[(size_t)cg*4096 + idx] * g_aux[(size_t)cg*192 + 64 + i];
    }
    __syncthreads();
    float kcol[NV];
    #pragma unroll
    for (int i = 0; i < NV; i++) {
        int t = i >> 1;
        const float* src = (i & 1) ? g_k1n : g_k0n;
        kcol[i] = src[(size_t)(base+t)*256 + d];
    }
    #pragma unroll
    for (int i = 0; i < NV; i++)
        g_BK[(size_t)cg*16384 + i*256 + d] = kcol[i] * g_aux[(size_t)cg*192 + i];
    #pragma unroll
    for (int t = 0; t < CL; t++)
        g_AQ[(size_t)cg*8192 + t*256 + d] =
            g_qn[(size_t)(base+t)*256 + d] * g_aux[(size_t)cg*192 + 128 + t];
    for (int jt = 0; jt < NV; jt += 16) {
        float acc[16];
        #pragma unroll
        for (int m = 0; m < 16; m++) acc[m] = 0.f;
        #pragma unroll
        for (int i = 0; i < NV; i++) {
            float kv = kcol[i];
            #pragma unroll
            for (int m4 = 0; m4 < 4; m4++) {
                float4 tv = *(const float4*)&Tsc[i][jt + m4*4];
                acc[m4*4+0] = fmaf(tv.x, kv, acc[m4*4+0]);
                acc[m4*4+1] = fmaf(tv.y, kv, acc[m4*4+1]);
                acc[m4*4+2] = fmaf(tv.z, kv, acc[m4*4+2]);
                acc[m4*4+3] = fmaf(tv.w, kv, acc[m4*4+3]);
            }
        }
        #pragma unroll
        for (int m = 0; m < 16; m++)
            g_CKT[(size_t)cg*16384 + (jt+m)*256 + d] = acc[m];
    }
}

// ---------------- chunked scan: 1 warp = 1 column, MLP-16 grouped GEMV passes ------
__global__ __launch_bounds__(128)
void scan_chunk()
{
    int bx = blockIdx.x;
    int b = bx >> 6;
    int colbase = (bx & 63) * 4;
    int w = threadIdx.x >> 5, lane = threadIdx.x & 31;
    int col = colbase + w;
    __shared__ float sAT[CL][65];
    __shared__ float part[4][64][33];
    __shared__ float rbuf[4][64];
    float s[8];
    #pragma unroll
    for (int e = 0; e < 8; e++) s[e] = 0.f;

    for (int cl = 0; cl < NCH; cl++) {
        int cg = b*NCH + cl;
        int base = b*Tt + cl*CL;
        __syncthreads();
        for (int idx = threadIdx.x; idx < CL*NV; idx += 128)
            sAT[idx >> 6][idx & 63] = g_AT[(size_t)cg*2048 + idx];
        __syncthreads();

        // ---- pass A: r-partials = BK * s0 (8-row groups, loads issued before use)
        {
            const float* BK = g_BK + (size_t)cg*16384 + lane*8;
            #pragma unroll
            for (int g = 0; g < 8; g++) {
                float4 a[8], c4[8];
                #pragma unroll
                for (int r = 0; r < 8; r++) {
                    const float* p = BK + (g*8 + r)*256;
                    a[r]  = *(const float4*)p;
                    c4[r] = *(const float4*)(p + 4);
                }
                #pragma unroll
                for (int r = 0; r < 8; r++) {
                    float pa = a[r].x*s[0] + a[r].y*s[1] + a[r].z*s[2] + a[r].w*s[3]
                             + c4[r].x*s[4] + c4[r].y*s[5] + c4[r].z*s[6] + c4[r].w*s[7];
                    part[w][g*8 + r][lane] = pa;
                }
            }
        }
        __syncwarp();
        float r1, r2;
        {
            float t1 = 0.f, t2 = 0.f;
            #pragma unroll
            for (int m = 0; m < 32; m++) {
                t1 += part[w][lane][m];
                t2 += part[w][lane+32][m];
            }
            int i1 = lane, i2 = lane + 32;
            float bv1 = g_v[(size_t)((base + (i1>>1))*2 + (i1&1))*256 + col];
            float bv2 = g_v[(size_t)((base + (i2>>1))*2 + (i2&1))*256 + col];
            r1 = bv1 - t1;
            r2 = bv2 - t2;
        }
        __syncwarp();
        // ---- pass B: qs0 = AQ * s0 (grouped)
        {
            const float* AQ = g_AQ + (size_t)cg*8192 + lane*8;
            #pragma unroll
            for (int g = 0; g < 4; g++) {
                float4 a[8], c4[8];
                #pragma unroll
                for (int r = 0; r < 8; r++) {
                    const float* p = AQ + (g*8 + r)*256;
                    a[r]  = *(const float4*)p;
                    c4[r] = *(const float4*)(p + 4);
                }
                #pragma unroll
                for (int r = 0; r < 8; r++) {
                    float pa = a[r].x*s[0] + a[r].y*s[1] + a[r].z*s[2] + a[r].w*s[3]
                             + c4[r].x*s[4] + c4[r].y*s[5] + c4[r].z*s[6] + c4[r].w*s[7];
                    part[w][g*8 + r][lane] = pa;
                }
            }
        }
        __syncwarp();
        float qs = 0.f;
        #pragma unroll
        for (int m = 0; m < 32; m++) qs += part[w][lane][m];
        rbuf[w][lane]      = r1;
        rbuf[w][lane + 32] = r2;
        __syncwarp();
        // ---- output o_t (t = lane): o = qs + sum_i AT[t][i] * r_i
        float o = qs;
        #pragma unroll
        for (int i = 0; i < NV; i++) o = fmaf(sAT[lane][i], rbuf[w][i], o);
        g_o[(size_t)(base + lane)*256 + col] = o;
        // ---- state: s = aend*s + sum_j CKT[j][.] * r_j (grouped)
        float aend = g_aux[(size_t)cg*192 + 160];
        #pragma unroll
        for (int e = 0; e < 8; e++) s[e] *= aend;
        {
            const float* CKT = g_CKT + (size_t)cg*16384 + lane*8;
            #pragma unroll
            for (int g = 0; g < 8; g++) {
                float4 a[8], c4[8];
                #pragma unroll
                for (int r = 0; r < 8; r++) {
                    const float* p = CKT + (g*8 + r)*256;
                    a[r]  = *(const float4*)p;
                    c4[r] = *(const float4*)(p + 4);
                }
                #pragma unroll
                for (int r = 0; r < 8; r++) {
                    float rj = rbuf[w][g*8 + r];
                    s[0] = fmaf(a[r].x,  rj, s[0]); s[1] = fmaf(a[r].y,  rj, s[1]);
                    s[2] = fmaf(a[r].z,  rj, s[2]); s[3] = fmaf(a[r].w,  rj, s[3]);
                    s[4] = fmaf(c4[r].x, rj, s[4]); s[5] = fmaf(c4[r].y, rj, s[5]);
                    s[6] = fmaf(c4[r].z, rj, s[6]); s[7] = fmaf(c4[r].w, rj, s[7]);
                }
            }
        }
    }
}

// ---------------- output rms-norm * o_norm_w * silu(gate), in place ----------------
__global__ __launch_bounds__(256)
void gate_kernel(const float* __restrict__ onw)
{
    int row = blockIdx.x, c = threadIdx.x;
    int lane = c & 31, w = c >> 5;
    float ov = g_o[(size_t)row*256 + c];
    __shared__ float red[8];
    float r = warp_sum(ov * ov);
    if (lane == 0) red[w] = r;
    __syncthreads();
    float sum = 0.f;
    #pragma unroll
    for (int i = 0; i < 8; i++) sum += red[i];
    float gt  = g_pack[(size_t)row*PW + 1280 + c];
    float res = ov * rsqrtf(sum * (1.f/256.f) + 1e-5f) * onw[c] * (gt / (1.f + expf(-gt)));
    g_o[(size_t)row*256 + c] = res;
}

// ---------------- launch ----------------
extern "C" void kernel_launch(void* const* d_in, const int* in_sizes, int n_in,
                              void* d_out, int out_size)
{
    const float* x       = (const float*)d_in[0];
    const float* Wq      = (const float*)d_in[1];
    const float* Wk      = (const float*)d_in[2];
    const float* Wv      = (const float*)d_in[3];
    const float* Wb      = (const float*)d_in[4];
    const float* Wa      = (const float*)d_in[5];
    const float* A_log   = (const float*)d_in[6];
    const float* dt_bias = (const float*)d_in[7];
    const float* qcw     = (const float*)d_in[8];
    const float* kcw     = (const float*)d_in[9];
    const float* vcw     = (const float*)d_in[10];
    const float* Wg      = (const float*)d_in[11];
    const float* onw     = (const float*)d_in[12];
    const float* Wo      = (const float*)d_in[13];
    float* out = (float*)d_out;

    float *pWpack, *pPack, *pO;
    cudaGetSymbolAddress((void**)&pWpack, g_Wpack);
    cudaGetSymbolAddress((void**)&pPack,  g_pack);
    cudaGetSymbolAddress((void**)&pO,     g_o);

    pack_weights<<<256, 256>>>(Wq, Wk, Wv, Wg);
    proj_small<<<ROWS/4, 128>>>(x, Wb, Wa, A_log, dt_bias);
    gemm_kernel<<<dim3(ROWS/64, PW/64), 256>>>(x, pWpack, pPack, 256, PW, PW);
    conv_norm_kernel<<<ROWS, 256>>>(qcw, kcw, vcw);
    gram_chunk<<<CHT, 256>>>();
    solve_chunk<<<CHT, 64>>>();
    build_chunk<<<CHT, 256>>>();
    scan_chunk<<<128, 128>>>();
    gate_kernel<<<ROWS, 256>>>(onw);
    gemm_kernel<<<dim3(ROWS/64, 256/64), 256>>>(pO, Wo, out, 256, 256, 256);
}

// round 9
// speedup vs baseline: 2.2090x; 2.2090x over previous
#include <cuda_runtime.h>
#include <math.h>

#define Bb   2
#define Tt   2048
#define ROWS (Bb*Tt)     // 4096
#define PW   1536        // packed width: q|k0|k1|v0|v1|gate

// ---------------- scratch (static device globals; no runtime alloc) ----------------
__device__ float g_Wpack[256 * PW];              // 1.5 MB
__device__ float g_pack[(size_t)ROWS * PW];      // 25.2 MB packed projections
__device__ float g_qn [ROWS * 256];              // normed q
__device__ float g_k0n[ROWS * 256];              // normed k (j=0)
__device__ float g_k1n[ROWS * 256];              // normed k (j=1)
__device__ float g_v  [ROWS * 2 * 256];          // silu'd v (j=0,1)
// per-step scalar record, 12 floats:
// 0 eg, 1 b0, 2 b1, 3 c10=k0.k1, 4 cq0=q.k0, 5 cq1=q.k1,
// 6 g00=k0.k0p, 7 g01=k0.k1p, 8 g10=k1.k0p, 9 g11=k1.k1p, 10 gq0=q.k0p, 11 gq1=q.k1p
__device__ float g_sc [ROWS * 12];
__device__ float g_o  [ROWS * 256];              // scan output, gated in place

__device__ __forceinline__ float warp_sum(float v) {
    #pragma unroll
    for (int off = 16; off; off >>= 1)
        v += __shfl_xor_sync(0xffffffffu, v, off);
    return v;
}

// ---------------- weight packing: [256][1536] ----------------
__global__ void pack_weights(const float* __restrict__ Wq, const float* __restrict__ Wk,
                             const float* __restrict__ Wv, const float* __restrict__ Wg)
{
    int d = blockIdx.x, c = threadIdx.x;
    g_Wpack[d*PW + c]        = Wq[d*256 + c];
    g_Wpack[d*PW + 256 + c]  = Wk[d*256 + c];
    g_Wpack[d*PW + 512 + c]  = Wk[65536 + d*256 + c];
    g_Wpack[d*PW + 768 + c]  = Wv[d*256 + c];
    g_Wpack[d*PW + 1024 + c] = Wv[65536 + d*256 + c];
    g_Wpack[d*PW + 1280 + c] = Wg[d*256 + c];
}

// ---------------- fp32 tiled GEMM: C[M,N] = A[M,256] * B[256,N] ----------------
// 128x64 tile, 256 threads, 8x4 microtile (32 FMA per 3 LDS.128), K fixed = 256
__global__ __launch_bounds__(256)
void gemm_kernel(const float* __restrict__ A, const float* __restrict__ B,
                 float* __restrict__ C, int lda, int ldb, int ldc)
{
    __shared__ float As[32][132];   // [k][row], padded (528B row, 16B aligned)
    __shared__ float Bs[32][64];
    int bm = blockIdx.x * 128, bn = blockIdx.y * 64;
    int tid = threadIdx.x;
    int tx = tid & 15, ty = tid >> 4;   // tx: col group (4 cols), ty: row group (8 rows)
    float acc[8][4] = {};
    for (int k0 = 0; k0 < 256; k0 += 32) {
        // A tile: 128 rows x 32 k = 1024 float4 loads, 4 per thread
        #pragma unroll
        for (int i = 0; i < 4; i++) {
            int idx = tid + i*256;
            int ar = idx >> 3, ac = (idx & 7) << 2;
            float4 av = *(const float4*)(A + (size_t)(bm+ar)*lda + k0 + ac);
            As[ac+0][ar] = av.x; As[ac+1][ar] = av.y;
            As[ac+2][ar] = av.z; As[ac+3][ar] = av.w;
        }
        // B tile: 32 k x 64 cols = 512 float4 loads, 2 per thread
        #pragma unroll
        for (int i = 0; i < 2; i++) {
            int idx = tid + i*256;
            int br = idx >> 4, bc = (idx & 15) << 2;
            *(float4*)(&Bs[br][bc]) = *(const float4*)(B + (size_t)(k0+br)*ldb + bn + bc);
        }
        __syncthreads();
        #pragma unroll
        for (int k = 0; k < 32; k++) {
            float a[8], b[4];
            *(float4*)(a)   = *(const float4*)(&As[k][ty*8]);
            *(float4*)(a+4) = *(const float4*)(&As[k][ty*8 + 4]);
            *(float4*)(b)   = *(const float4*)(&Bs[k][tx*4]);
            #pragma unroll
            for (int i = 0; i < 8; i++)
                #pragma unroll
                for (int j = 0; j < 4; j++)
                    acc[i][j] = fmaf(a[i], b[j], acc[i][j]);
        }
        __syncthreads();
    }
    #pragma unroll
    for (int i = 0; i < 8; i++)
        *(float4*)(C + (size_t)(bm + ty*8 + i)*ldc + bn + tx*4) = *(float4*)acc[i];
}

// ---------------- beta / g projections -> scalar record [0..2] ----------------
__global__ void proj_small(const float* __restrict__ x, const float* __restrict__ Wb,
                           const float* __restrict__ Wa, const float* __restrict__ A_log,
                           const float* __restrict__ dt_bias)
{
    int row  = blockIdx.x * 4 + (threadIdx.x >> 5);
    int lane = threadIdx.x & 31;
    const float* xr = x + (size_t)row * 256;
    float a0 = 0.f, a1 = 0.f, a2 = 0.f;
    #pragma unroll
    for (int r = 0; r < 8; r++) {
        int d = lane + 32*r;
        float xv = xr[d];
        a0 = fmaf(xv, Wb[d],       a0);
        a1 = fmaf(xv, Wb[256 + d], a1);
        a2 = fmaf(xv, Wa[d],       a2);
    }
    a0 = warp_sum(a0); a1 = warp_sum(a1); a2 = warp_sum(a2);
    if (lane == 0) {
        float z  = a2 + dt_bias[0];
        float sp = (z > 20.f) ? z : log1pf(expf(z));
        float g  = -expf(A_log[0]) * sp;
        g_sc[row*12 + 0] = expf(g);                 // eg
        g_sc[row*12 + 1] = 1.f / (1.f + expf(-a0)); // b0
        g_sc[row*12 + 2] = 1.f / (1.f + expf(-a1)); // b1
    }
}

// ---------------- causal conv4 + silu + l2norm + same-step dot scalars ----------------
__global__ __launch_bounds__(256)
void conv_norm_kernel(const float* __restrict__ qw, const float* __restrict__ kw,
                      const float* __restrict__ vw)
{
    int row = blockIdx.x;
    int t   = row & (Tt - 1);
    int c   = threadIdx.x;
    int lane = c & 31, w = c >> 5;
    float acc[5] = {0.f, 0.f, 0.f, 0.f, 0.f};
    #pragma unroll
    for (int i = 0; i < 4; i++) {
        if (t - 3 + i < 0) continue;
        const float* Pr = g_pack + (size_t)(row - 3 + i) * PW;
        acc[0] = fmaf(Pr[c],        qw[c*4 + i],          acc[0]);
        acc[1] = fmaf(Pr[256 + c],  kw[c*4 + i],          acc[1]);
        acc[2] = fmaf(Pr[512 + c],  kw[(256 + c)*4 + i],  acc[2]);
        acc[3] = fmaf(Pr[768 + c],  vw[c*4 + i],          acc[3]);
        acc[4] = fmaf(Pr[1024 + c], vw[(256 + c)*4 + i],  acc[4]);
    }
    #pragma unroll
    for (int m = 0; m < 5; m++) acc[m] = acc[m] / (1.f + expf(-acc[m]));  // silu

    __shared__ float red[3][8];
    float r0 = warp_sum(acc[0]*acc[0]);
    float r1 = warp_sum(acc[1]*acc[1]);
    float r2 = warp_sum(acc[2]*acc[2]);
    if (lane == 0) { red[0][w] = r0; red[1][w] = r1; red[2][w] = r2; }
    __syncthreads();
    float s0 = 0.f, s1 = 0.f, s2 = 0.f;
    #pragma unroll
    for (int i = 0; i < 8; i++) { s0 += red[0][i]; s1 += red[1][i]; s2 += red[2][i]; }
    float qv  = acc[0] * rsqrtf(s0 + 1e-6f);
    float k0v = acc[1] * rsqrtf(s1 + 1e-6f);
    float k1v = acc[2] * rsqrtf(s2 + 1e-6f);
    __syncthreads();
    r0 = warp_sum(k0v * k1v);
    r1 = warp_sum(qv * k0v);
    r2 = warp_sum(qv * k1v);
    if (lane == 0) { red[0][w] = r0; red[1][w] = r1; red[2][w] = r2; }
    __syncthreads();
    s0 = 0.f; s1 = 0.f; s2 = 0.f;
    #pragma unroll
    for (int i = 0; i < 8; i++) { s0 += red[0][i]; s1 += red[1][i]; s2 += red[2][i]; }
    if (c == 0) { g_sc[row*12 + 3] = s0; g_sc[row*12 + 4] = s1; g_sc[row*12 + 5] = s2; }

    g_qn [row*256 + c] = qv;
    g_k0n[row*256 + c] = k0v;
    g_k1n[row*256 + c] = k1v;
    g_v[(size_t)(row*2 + 0)*256 + c] = acc[3];
    g_v[(size_t)(row*2 + 1)*256 + c] = acc[4];
}

// ---------------- adjacent-step Gram scalars -> record [6..11] ----------------
__global__ __launch_bounds__(256)
void gram_kernel()
{
    int row = blockIdx.x;
    int t = row & (Tt - 1);
    int c = threadIdx.x, lane = c & 31, w = c >> 5;
    float qv = 0.f, k0v = 0.f, k1v = 0.f, p0 = 0.f, p1 = 0.f;
    if (t > 0) {
        qv  = g_qn [row*256 + c];
        k0v = g_k0n[row*256 + c];
        k1v = g_k1n[row*256 + c];
        p0  = g_k0n[(row-1)*256 + c];
        p1  = g_k1n[(row-1)*256 + c];
    }
    float r[6] = { k0v*p0, k0v*p1, k1v*p0, k1v*p1, qv*p0, qv*p1 };
    __shared__ float red[6][8];
    #pragma unroll
    for (int m = 0; m < 6; m++) r[m] = warp_sum(r[m]);
    if (lane == 0)
        #pragma unroll
        for (int m = 0; m < 6; m++) red[m][w] = r[m];
    __syncthreads();
    if (c < 6) {
        float s = 0.f;
        #pragma unroll
        for (int i = 0; i < 8; i++) s += red[c][i];
        g_sc[row*12 + 6 + c] = s;
    }
}

// ---------------- scan: 1 warp = 1 value-column; reductions pipelined 2 ahead -------
#define LDV(arr, row, dst) do {                                               \
    const float4* _p = (const float4*)(arr + (size_t)(row)*256 + lane*8);     \
    float4 _a = _p[0], _b = _p[1];                                            \
    dst[0]=_a.x; dst[1]=_a.y; dst[2]=_a.z; dst[3]=_a.w;                       \
    dst[4]=_b.x; dst[5]=_b.y; dst[6]=_b.z; dst[7]=_b.w; } while (0)

#define STEP(i) {                                                             \
    const int t = t0 + (i); const int p = (i)&1; const int jb = ((i)+2)&3;    \
    float eg=sc0[p].x, b0v=sc0[p].y, b1v=sc0[p].z, c10=sc0[p].w;              \
    float cq0=sc1[p].x, cq1=sc1[p].y, g00=sc1[p].z, g01=sc1[p].w;             \
    float g10=sc2[p].x, g11=sc2[p].y, gq0=sc2[p].z, gq1=sc2[p].w;             \
    float kS0 = fmaf(egp, d0[p], fmaf(g00, u0p, g01*u1p));                    \
    float kS1 = fmaf(egp, d1[p], fmaf(g10, u0p, g11*u1p));                    \
    float qS  = fmaf(egp, dq[p], fmaf(gq0, u0p, gq1*u1p));                    \
    float u0 = b0v * fmaf(-eg, kS0, vv0[p]);                                  \
    float u1 = b1v * (vv1[p] - eg*kS1 - c10*u0);                              \
    float ov = fmaf(eg, qS, fmaf(cq0, u0, cq1*u1));                           \
    if (lane == 0) g_o[(size_t)(base + t)*256 + col] = ov;                    \
    _Pragma("unroll")                                                         \
    for (int r = 0; r < 8; r++)                                               \
        s[r] = fmaf(k1b[i][r], u1, fmaf(k0b[i][r], u0, eg*s[r]));             \
    u0p = u0; u1p = u1; egp = eg;                                             \
    {   int rl = base + ((t+4 < Tt) ? (t+4) : (Tt-1));                        \
        LDV(g_qn, rl, qb[i]); LDV(g_k0n, rl, k0b[i]); LDV(g_k1n, rl, k1b[i]); \
        int rs = base + ((t+2 < Tt) ? (t+2) : (Tt-1));                        \
        sc0[p] = *(const float4*)(g_sc + (size_t)rs*12);                      \
        sc1[p] = *(const float4*)(g_sc + (size_t)rs*12 + 4);                  \
        sc2[p] = *(const float4*)(g_sc + (size_t)rs*12 + 8);                  \
        vv0[p] = g_v[(size_t)rs*512 + col];                                   \
        vv1[p] = g_v[(size_t)rs*512 + 256 + col]; }                           \
    float m0a=0.f,m0b=0.f,m1a=0.f,m1b=0.f,mqa=0.f,mqb=0.f;                    \
    _Pragma("unroll")                                                         \
    for (int r = 0; r < 8; r += 2) {                                          \
        m0a = fmaf(s[r],   k0b[jb][r],   m0a);                                \
        m0b = fmaf(s[r+1], k0b[jb][r+1], m0b);                                \
        m1a = fmaf(s[r],   k1b[jb][r],   m1a);                                \
        m1b = fmaf(s[r+1], k1b[jb][r+1], m1b);                                \
        mqa = fmaf(s[r],   qb[jb][r],    mqa);                                \
        mqb = fmaf(s[r+1], qb[jb][r+1],  mqb); }                              \
    float m0_ = m0a+m0b, m1_ = m1a+m1b, mq_ = mqa+mqb;                        \
    _Pragma("unroll")                                                         \
    for (int off = 16; off; off >>= 1) {                                      \
        m0_ += __shfl_xor_sync(0xffffffffu, m0_, off);                        \
        m1_ += __shfl_xor_sync(0xffffffffu, m1_, off);                        \
        mq_ += __shfl_xor_sync(0xffffffffu, mq_, off); }                      \
    d0[p] = m0_; d1[p] = m1_; dq[p] = mq_;                                    \
}

__global__ __launch_bounds__(128)
void scan_kernel()
{
    int b    = blockIdx.y;
    int lane = threadIdx.x & 31;
    int col  = blockIdx.x * 4 + (threadIdx.x >> 5);   // 0..255
    int base = b * Tt;

    float s[8];
    #pragma unroll
    for (int r = 0; r < 8; r++) s[r] = 0.f;

    float qb[4][8], k0b[4][8], k1b[4][8];
    float4 sc0[2], sc1[2], sc2[2];
    float vv0[2], vv1[2];
    float dq[2] = {0.f, 0.f}, d0[2] = {0.f, 0.f}, d1[2] = {0.f, 0.f};
    float u0p = 0.f, u1p = 0.f, egp = 0.f;

    #pragma unroll
    for (int i = 0; i < 4; i++) {
        int row = base + i;
        LDV(g_qn, row, qb[i]); LDV(g_k0n, row, k0b[i]); LDV(g_k1n, row, k1b[i]);
    }
    #pragma unroll
    for (int p = 0; p < 2; p++) {
        int row = base + p;
        sc0[p] = *(const float4*)(g_sc + (size_t)row*12);
        sc1[p] = *(const float4*)(g_sc + (size_t)row*12 + 4);
        sc2[p] = *(const float4*)(g_sc + (size_t)row*12 + 8);
        vv0[p] = g_v[(size_t)row*512 + col];
        vv1[p] = g_v[(size_t)row*512 + 256 + col];
    }

    for (int t0 = 0; t0 < Tt; t0 += 4) {
        STEP(0) STEP(1) STEP(2) STEP(3)
    }
}

// ---------------- output rms-norm * o_norm_w * silu(gate), in place ----------------
__global__ __launch_bounds__(256)
void gate_kernel(const float* __restrict__ onw)
{
    int row = blockIdx.x, c = threadIdx.x;
    int lane = c & 31, w = c >> 5;
    float ov = g_o[(size_t)row*256 + c];
    __shared__ float red[8];
    float r = warp_sum(ov * ov);
    if (lane == 0) red[w] = r;
    __syncthreads();
    float sum = 0.f;
    #pragma unroll
    for (int i = 0; i < 8; i++) sum += red[i];
    float gt  = g_pack[(size_t)row*PW + 1280 + c];
    float res = ov * rsqrtf(sum * (1.f/256.f) + 1e-5f) * onw[c] * (gt / (1.f + expf(-gt)));
    g_o[(size_t)row*256 + c] = res;
}

// ---------------- launch ----------------
extern "C" void kernel_launch(void* const* d_in, const int* in_sizes, int n_in,
                              void* d_out, int out_size)
{
    const float* x       = (const float*)d_in[0];
    const float* Wq      = (const float*)d_in[1];
    const float* Wk      = (const float*)d_in[2];
    const float* Wv      = (const float*)d_in[3];
    const float* Wb      = (const float*)d_in[4];
    const float* Wa      = (const float*)d_in[5];
    const float* A_log   = (const float*)d_in[6];
    const float* dt_bias = (const float*)d_in[7];
    const float* qcw     = (const float*)d_in[8];
    const float* kcw     = (const float*)d_in[9];
    const float* vcw     = (const float*)d_in[10];
    const float* Wg      = (const float*)d_in[11];
    const float* onw     = (const float*)d_in[12];
    const float* Wo      = (const float*)d_in[13];
    float* out = (float*)d_out;

    float *pWpack, *pPack, *pO;
    cudaGetSymbolAddress((void**)&pWpack, g_Wpack);
    cudaGetSymbolAddress((void**)&pPack,  g_pack);
    cudaGetSymbolAddress((void**)&pO,     g_o);

    pack_weights<<<256, 256>>>(Wq, Wk, Wv, Wg);
    proj_small<<<ROWS/4, 128>>>(x, Wb, Wa, A_log, dt_bias);
    gemm_kernel<<<dim3(ROWS/128, PW/64), 256>>>(x, pWpack, pPack, 256, PW, PW);
    conv_norm_kernel<<<ROWS, 256>>>(qcw, kcw, vcw);
    gram_kernel<<<ROWS, 256>>>();
    scan_kernel<<<dim3(64, Bb), 128>>>();
    gate_kernel<<<ROWS, 256>>>(onw);
    gemm_kernel<<<dim3(ROWS/128, 256/64), 256>>>(pO, Wo, out, 256, 256, 256);
}